// round 4
// baseline (speedup 1.0000x reference)
#include <cuda_runtime.h>
#include <math.h>

#define N_BOX 3000
#define NTHREADS 512
#define NWARPS (NTHREADS / 32)                      // 16
#define MAX_E ((N_BOX + NTHREADS - 1) / NTHREADS)   // 6
#define FULL_MASK 0xFFFFFFFFu
typedef unsigned long long u64;

// smem: float4 sbox[N] (read-only after init) | float sar[N] | u64 part[2][NWARPS]
#define SMEM_BYTES (16 * N_BOX + 4 * N_BOX + 8 * 2 * NWARPS)

__global__ void __launch_bounds__(NTHREADS, 1)
softnms_kernel(const float4* __restrict__ g_boxes,
               const float*  __restrict__ g_scores,
               const int*    __restrict__ g_idxs,
               float* __restrict__ out)
{
    extern __shared__ unsigned char smem_raw[];
    float4* sbox = (float4*)smem_raw;
    float*  sar  = (float*)(sbox + N_BOX);
    u64*    part = (u64*)(sar + N_BOX);   // [2][NWARPS] parity double-buffer

    const int tid  = threadIdx.x;
    const int lane = tid & 31;
    const int warp = tid >> 5;

    // ---- 1) max_coord over all 4N coords (max is rounding-free) ------------
    const float* gb = (const float*)g_boxes;
    float m = -INFINITY;
    for (int k = tid; k < 4 * N_BOX; k += NTHREADS) m = fmaxf(m, gb[k]);
    #pragma unroll
    for (int o = 16; o; o >>= 1) m = fmaxf(m, __shfl_down_sync(FULL_MASK, m, o));
    if (lane == 0) ((float*)part)[warp] = m;
    __syncthreads();
    if (warp == 0) {
        float v = (lane < NWARPS) ? ((float*)part)[lane] : -INFINITY;
        #pragma unroll
        for (int o = 16; o; o >>= 1) v = fmaxf(v, __shfl_down_sync(FULL_MASK, v, o));
        if (lane == 0) ((float*)part)[0] = v;
    }
    __syncthreads();
    const float off_scale = __fadd_rn(((float*)part)[0], 1.0f);   // max_coord + 1
    __syncthreads();   // done reusing part as float scratch

    // ---- 2) register-resident elements; smem copy only for winner bcast ----
    // Exact XLA order: off = idx*scale (1 rounding); coord+off (1 rounding).
    float ex1[MAX_E], ey1[MAX_E], ex2[MAX_E], ey2[MAX_E], ear[MAX_E], esc[MAX_E];
    int   epos[MAX_E];          // current slot of element (starts = orig index)
    unsigned alive = 0;         // bit e: element exists and not yet selected

    u64 best = 0;
    #pragma unroll
    for (int e = 0; e < MAX_E; e++) {
        int k = tid + e * NTHREADS;   // orig index (fixed ownership)
        if (k < N_BOX) {
            float4 b = g_boxes[k];
            float off = __fmul_rn((float)g_idxs[k], off_scale);
            b.x = __fadd_rn(b.x, off); b.y = __fadd_rn(b.y, off);
            b.z = __fadd_rn(b.z, off); b.w = __fadd_rn(b.w, off);
            float area = __fmul_rn(__fsub_rn(b.z, b.x), __fsub_rn(b.w, b.y));
            sbox[k] = b; sar[k] = area;
            ex1[e] = b.x; ey1[e] = b.y; ex2[e] = b.z; ey2[e] = b.w;
            ear[e] = area; esc[e] = g_scores[k]; epos[e] = k;
            alive |= 1u << e;
            // key: score_bits desc | slot asc (via ~pos) | orig (id only).
            // scores >= 0 so f32 bits are order-preserving; slots are unique
            // so exact score ties break toward the smallest slot (jnp.argmax).
            u64 key = ((u64)__float_as_uint(esc[e]) << 24)
                    | ((u64)(0xFFFu - (unsigned)k) << 12) | (unsigned)k;
            if (key > best) best = key;
        }
    }
    #pragma unroll
    for (int o = 16; o; o >>= 1) {
        u64 v = __shfl_down_sync(FULL_MASK, best, o);
        if (v > best) best = v;
    }
    if (lane == 0) part[warp] = best;   // parity-0 buffer
    __syncthreads();

    // ---- 3) main loop: ONE barrier per iteration ---------------------------
    int par = 0;
    for (int i = 0; i < N_BOX; i++) {
        // every warp redundantly reduces the 16 partials (covers all unselected)
        u64 v = (lane < NWARPS) ? part[par * NWARPS + lane] : 0;
        #pragma unroll
        for (int o = 8; o; o >>= 1) {
            u64 u = __shfl_down_sync(FULL_MASK, v, o);
            if (u > v) v = u;
        }
        v = __shfl_sync(FULL_MASK, v, 0);
        const int orig_j = (int)(v & 0xFFFu);
        const int pos_j  = 0xFFF - (int)((v >> 12) & 0xFFFu);   // winner's slot

        // winner's score is final at selection time -> stream outputs now
        if (tid == 0) {
            float sj = __uint_as_float((unsigned)(v >> 24));
            out[i]             = sj;
            out[N_BOX + i]     = (float)orig_j;
            out[2 * N_BOX + i] = (sj > 0.05f) ? 1.0f : 0.0f;
        }

        const float4 bb = sbox[orig_j];   // broadcast LDS, conflict-free
        const float  ba = sar[orig_j];

        best = 0;
        #pragma unroll
        for (int e = 0; e < MAX_E; e++) {
            int k = tid + e * NTHREADS;
            if (!(alive & (1u << e))) continue;
            if (k == orig_j) { alive &= ~(1u << e); continue; }  // retire winner
            if (epos[e] == i) epos[e] = pos_j;   // element at slot i moves to winner's slot
            // exact reference arithmetic (all _rn, same eval order):
            float iw = __fsub_rn(fminf(bb.z, ex2[e]), fmaxf(bb.x, ex1[e]));
            float ih = __fsub_rn(fminf(bb.w, ey2[e]), fmaxf(bb.y, ey1[e]));
            float sc = esc[e];
            if (iw > 0.0f && ih > 0.0f) {        // iou==0 => decay==1 exactly
                float inter = __fmul_rn(iw, ih);
                float denom = __fsub_rn(__fadd_rn(ba, ear[e]), inter);
                float iou   = __fdiv_rn(inter, denom);
                float arg   = __fmul_rn(-__fmul_rn(iou, iou), 2.0f); // == /0.5
                sc = __fmul_rn(sc, expf(arg));                        // libdevice
                esc[e] = sc;
            }
            u64 key = ((u64)__float_as_uint(sc) << 24)
                    | ((u64)(0xFFFu - (unsigned)epos[e]) << 12) | (unsigned)k;
            if (key > best) best = key;
        }
        #pragma unroll
        for (int o = 16; o; o >>= 1) {
            u64 u = __shfl_down_sync(FULL_MASK, best, o);
            if (u > best) best = u;
        }
        par ^= 1;
        if (lane == 0) part[par * NWARPS + warp] = best;
        __syncthreads();   // the single per-iteration barrier
    }
}

extern "C" void kernel_launch(void* const* d_in, const int* in_sizes, int n_in,
                              void* d_out, int out_size) {
    (void)in_sizes; (void)n_in; (void)out_size;
    cudaFuncSetAttribute(softnms_kernel,
                         cudaFuncAttributeMaxDynamicSharedMemorySize, SMEM_BYTES);
    softnms_kernel<<<1, NTHREADS, SMEM_BYTES>>>(
        (const float4*)d_in[0],
        (const float*)d_in[1],
        (const int*)d_in[2],
        (float*)d_out);
}

// round 5
// speedup vs baseline: 19.8712x; 19.8712x over previous
#include <cuda_runtime.h>
#include <math.h>

#define N_BOX  3000
#define NPAD   4096
#define NCLASS 80
#define DEG    96
#define FULL_MASK 0xFFFFFFFFu
typedef unsigned long long u64;
typedef unsigned int u32;

// persistent scratch (re-initialized every launch; no allocations)
__device__ float4 d_obox[N_BOX];
__device__ float  d_area[N_BOX];
__device__ float  d_sc[N_BOX];           // working scores
__device__ float  d_fs[N_BOX];           // final (at-selection) scores
__device__ int    d_cls[N_BOX];
__device__ int    d_cls_start[NCLASS + 1];
__device__ int    d_cls_sorted[N_BOX];
__device__ int    d_label[N_BOX];
__device__ int    d_deg[N_BOX];
__device__ int    d_adj_idx[N_BOX * DEG];
__device__ float  d_adj_dec[N_BOX * DEG];
__device__ int    d_cstart[N_BOX];
__device__ int    d_ccnt[N_BOX];
__device__ int    d_cmember[N_BOX];

// ---- K1: max_coord, offset boxes, areas, class bucketing (1 block) --------
__global__ void __launch_bounds__(1024, 1)
k_prep(const float4* __restrict__ gb, const float* __restrict__ gs,
       const int* __restrict__ gi)
{
    __shared__ float red[32];
    __shared__ int   cnt[NCLASS];
    __shared__ int   cur[NCLASS];
    __shared__ float s_off;
    const int tid = threadIdx.x, lane = tid & 31, w = tid >> 5;

    const float* f = (const float*)gb;
    float m = -INFINITY;
    for (int k = tid; k < 4 * N_BOX; k += 1024) m = fmaxf(m, f[k]);
    #pragma unroll
    for (int o = 16; o; o >>= 1) m = fmaxf(m, __shfl_down_sync(FULL_MASK, m, o));
    if (lane == 0) red[w] = m;
    if (tid < NCLASS) cnt[tid] = 0;
    __syncthreads();
    if (w == 0) {
        float v = red[lane];
        #pragma unroll
        for (int o = 16; o; o >>= 1) v = fmaxf(v, __shfl_down_sync(FULL_MASK, v, o));
        if (lane == 0) s_off = __fadd_rn(v, 1.0f);   // max_coord + 1 (exact max)
    }
    __syncthreads();
    const float off_scale = s_off;

    for (int k = tid; k < N_BOX; k += 1024) {
        float4 b = gb[k];
        int c = gi[k];
        float off = __fmul_rn((float)c, off_scale);   // exact XLA order
        b.x = __fadd_rn(b.x, off); b.y = __fadd_rn(b.y, off);
        b.z = __fadd_rn(b.z, off); b.w = __fadd_rn(b.w, off);
        d_obox[k] = b;
        d_area[k] = __fmul_rn(__fsub_rn(b.z, b.x), __fsub_rn(b.w, b.y));
        d_sc[k]   = gs[k];
        d_cls[k]  = c;
        atomicAdd(&cnt[c], 1);
    }
    __syncthreads();
    if (tid == 0) {
        int acc = 0;
        for (int c = 0; c < NCLASS; c++) { d_cls_start[c] = acc; cur[c] = acc; acc += cnt[c]; }
        d_cls_start[NCLASS] = acc;
    }
    __syncthreads();
    for (int k = tid; k < N_BOX; k += 1024) {
        int p = atomicAdd(&cur[d_cls[k]], 1);
        d_cls_sorted[p] = k;
    }
}

// ---- K2: same-class overlap adjacency + precomputed decay (grid) ----------
__global__ void k_adj()
{
    int k = blockIdx.x * blockDim.x + threadIdx.x;
    if (k >= N_BOX) return;
    float4 b = d_obox[k];
    float  ba = d_area[k];
    int c = d_cls[k];
    int s = d_cls_start[c], e = d_cls_start[c + 1];
    int dg = 0;
    for (int t = s; t < e; t++) {
        int j = d_cls_sorted[t];
        if (j == k) continue;
        float4 o = d_obox[j];
        float iw = __fsub_rn(fminf(b.z, o.z), fmaxf(b.x, o.x));
        float ih = __fsub_rn(fminf(b.w, o.w), fmaxf(b.y, o.y));
        if (iw > 0.0f && ih > 0.0f) {
            // exact reference arithmetic: area_a(winner=k) + area_b - inter
            float inter = __fmul_rn(iw, ih);
            float den   = __fsub_rn(__fadd_rn(ba, d_area[j]), inter);
            float iou   = __fdiv_rn(inter, den);
            float arg   = __fmul_rn(-__fmul_rn(iou, iou), 2.0f);   // == /0.5
            if (dg < DEG) {
                d_adj_idx[k * DEG + dg] = j;
                d_adj_dec[k * DEG + dg] = expf(arg);               // libdevice
                dg++;
            }
        }
    }
    d_deg[k] = dg;
}

// ---- K3: connected components + per-component CSR (1 block) ---------------
__global__ void __launch_bounds__(1024, 1)
k_comp()
{
    __shared__ int lab[N_BOX];
    __shared__ int cs[N_BOX];
    __shared__ int wsum[32];
    const int tid = threadIdx.x, lane = tid & 31, w = tid >> 5;

    for (int k = tid; k < N_BOX; k += 1024) lab[k] = k;
    __syncthreads();
    // min-label propagation with pointer jumping; monotone -> races benign
    for (int it = 0; it < 20; it++) {
        for (int k = tid; k < N_BOX; k += 1024) {
            int l = lab[k];
            int l2 = lab[l]; if (l2 < l) l = l2;
            int dg = d_deg[k];
            for (int t = 0; t < dg; t++) {
                int jl = lab[d_adj_idx[k * DEG + t]];
                if (jl < l) l = jl;
            }
            atomicMin(&lab[k], l);
        }
        __syncthreads();
    }
    // counts per root label
    for (int k = tid; k < N_BOX; k += 1024) cs[k] = 0;
    __syncthreads();
    for (int k = tid; k < N_BOX; k += 1024) atomicAdd(&cs[lab[k]], 1);
    __syncthreads();
    for (int k = tid; k < N_BOX; k += 1024) d_ccnt[k] = cs[k];
    __syncthreads();
    // exclusive scan of cs[0..2999]; thread t<1000 owns [3t, 3t+3)
    int c0 = 0, c1 = 0, c2 = 0, lsum = 0;
    if (tid < 1000) {
        c0 = cs[3 * tid]; c1 = cs[3 * tid + 1]; c2 = cs[3 * tid + 2];
        lsum = c0 + c1 + c2;
    }
    int inc = lsum;
    #pragma unroll
    for (int o = 1; o < 32; o <<= 1) {
        int v = __shfl_up_sync(FULL_MASK, inc, o);
        if (lane >= o) inc += v;
    }
    if (lane == 31) wsum[w] = inc;
    __syncthreads();
    if (w == 0) {
        int v = wsum[lane];
        int iv = v;
        #pragma unroll
        for (int o = 1; o < 32; o <<= 1) {
            int u = __shfl_up_sync(FULL_MASK, iv, o);
            if (lane >= o) iv += u;
        }
        wsum[lane] = iv - v;   // exclusive warp bases
    }
    __syncthreads();
    if (tid < 1000) {
        int base = wsum[w] + (inc - lsum);   // exclusive for this thread
        cs[3 * tid]     = base;
        cs[3 * tid + 1] = base + c0;
        cs[3 * tid + 2] = base + c0 + c1;
        d_cstart[3 * tid]     = base;
        d_cstart[3 * tid + 1] = base + c0;
        d_cstart[3 * tid + 2] = base + c0 + c1;
    }
    __syncthreads();
    // scatter members (cs doubles as cursor)
    for (int k = tid; k < N_BOX; k += 1024) {
        int p = atomicAdd(&cs[lab[k]], 1);
        d_cmember[p] = k;
        d_label[k] = lab[k];
    }
}

// ---- K4: per-component sequential soft-NMS (thread per root) --------------
__global__ void k_nms()
{
    int k = blockIdx.x * blockDim.x + threadIdx.x;
    if (k >= N_BOX) return;
    if (d_label[k] != k) return;        // roots only
    int m = d_ccnt[k];
    int s = d_cstart[k];
    if (m == 1) { d_fs[k] = d_sc[k]; return; }
    for (int t = 0; t < m; t++) {
        float best = -INFINITY; int wdx = -1;
        for (int q = 0; q < m; q++) {
            int j = d_cmember[s + q];
            float v = d_sc[j];
            if (v > best) { best = v; wdx = j; }
        }
        d_fs[wdx] = best;
        d_sc[wdx] = -INFINITY;          // retire winner
        int dg = d_deg[wdx];
        for (int q = 0; q < dg; q++) {
            int j = d_adj_idx[wdx * DEG + q];
            float v = d_sc[j];
            if (v > -INFINITY)          // only unselected decay
                d_sc[j] = __fmul_rn(v, d_adj_dec[wdx * DEG + q]);
        }
    }
}

// ---- K5: bitonic sort by final score desc + outputs (1 block) -------------
__global__ void __launch_bounds__(1024, 1)
k_sort(float* __restrict__ out)
{
    __shared__ u64 key[NPAD];
    const int tid = threadIdx.x;
    for (int i = tid; i < NPAD; i += 1024) {
        if (i < N_BOX)
            key[i] = ((u64)__float_as_uint(d_fs[i]) << 32)
                   | (u64)(0xFFFFFFFFu - (u32)i);   // ties -> smaller idx first
        else
            key[i] = 0;
    }
    __syncthreads();
    for (int kk = 2; kk <= NPAD; kk <<= 1) {
        for (int j = kk >> 1; j > 0; j >>= 1) {
            for (int i = tid; i < NPAD; i += 1024) {
                int ix = i ^ j;
                if (ix > i) {
                    u64 a = key[i], b = key[ix];
                    bool up = ((i & kk) == 0);
                    if ((a < b) == up) { key[i] = b; key[ix] = a; }   // descending
                }
            }
            __syncthreads();
        }
    }
    for (int i = tid; i < N_BOX; i += 1024) {
        u64 kv = key[i];
        float s = __uint_as_float((u32)(kv >> 32));
        int idx = (int)(0xFFFFFFFFu - (u32)(kv & 0xFFFFFFFFu));
        out[i]             = s;
        out[N_BOX + i]     = (float)idx;
        out[2 * N_BOX + i] = (s > 0.05f) ? 1.0f : 0.0f;
    }
}

extern "C" void kernel_launch(void* const* d_in, const int* in_sizes, int n_in,
                              void* d_out, int out_size) {
    (void)in_sizes; (void)n_in; (void)out_size;
    const float4* boxes = (const float4*)d_in[0];
    const float*  scores = (const float*)d_in[1];
    const int*    idxs = (const int*)d_in[2];
    float* out = (float*)d_out;

    k_prep<<<1, 1024>>>(boxes, scores, idxs);
    k_adj<<<(N_BOX + 255) / 256, 256>>>();
    k_comp<<<1, 1024>>>();
    k_nms<<<(N_BOX + 255) / 256, 256>>>();
    k_sort<<<1, 1024>>>(out);
}